// round 10
// baseline (speedup 1.0000x reference)
#include <cuda_runtime.h>

#define NB     16384
#define NNODES 55
#define NTOT   (NB * NNODES)      // 901120
#define ECNT   (4 * NTOT)         // 3604480
#define SCAN_CH 4096
#define SCAN_NB (NTOT / SCAN_CH)  // 220 exactly

#define AGG_BLOCKS 7040           // 7040 * 8 warps * 16 nodes = 901120

// ---------------- device scratch ----------------
__device__ float g_paA[NTOT * 32];
__device__ float g_psA[NTOT * 32];
__device__ float g_paB[NTOT * 32];
__device__ float g_psB[NTOT * 32];
__device__ float g_jk[NTOT * 32];
__device__ int   g_deg[NTOT];
__device__ int   g_rowptr[NTOT];
__device__ int   g_cursor[NTOT];
__device__ int   g_col[ECNT];
__device__ int   g_bsum[256];
__device__ float g_A[1024], g_W2[1024], g_u[32], g_v[32], g_b2[32], g_c[1];

__device__ __forceinline__ float selu_f(float x) {
    const float sc = 1.0507009873554805f;
    const float sa = 1.7580993408473766f;  // sc * alpha
    return x > 0.f ? sc * x : sa * expm1f(x);
}

// ---------------- attention precompute ----------------
__global__ void __launch_bounds__(256) k_prep(
        const float* __restrict__ wq, const float* __restrict__ bq,
        const float* __restrict__ wk, const float* __restrict__ bk,
        const float* __restrict__ wv, const float* __restrict__ bv,
        const float* __restrict__ wo, const float* __restrict__ bo) {
    int tid = threadIdx.x;
    for (int i = tid; i < 1024; i += 256) {
        int d = i >> 5, e = i & 31;
        float a = 0.f, w2 = 0.f;
        for (int o = 0; o < 32; o++) {
            a  += wq[d * 32 + o] * wk[e * 32 + o];
            w2 += wv[d * 32 + o] * wo[o * 32 + e];
        }
        g_A[d * 32 + e]  = a;
        g_W2[d * 32 + e] = w2;
    }
    if (tid < 32) {
        float u = 0.f, v = 0.f, b2 = 0.f;
        for (int o = 0; o < 32; o++) {
            u  += wq[tid * 32 + o] * bk[o];
            v  += wk[tid * 32 + o] * bq[o];
            b2 += bv[o] * wo[o * 32 + tid];
        }
        g_u[tid] = u; g_v[tid] = v; g_b2[tid] = b2 + bo[tid];
    }
    if (tid == 0) {
        float c = 0.f;
        for (int o = 0; o < 32; o++) c += bq[o] * bk[o];
        g_c[0] = c;
    }
}

// ---------------- CSR build ----------------
__global__ void __launch_bounds__(256) k_zero() {
    int i = blockIdx.x * blockDim.x + threadIdx.x;
    if (i < NTOT) g_deg[i] = 0;
}
__global__ void __launch_bounds__(256) k_hist(const int* __restrict__ ei) {
    int e = blockIdx.x * blockDim.x + threadIdx.x;
    if (e < ECNT) atomicAdd(&g_deg[ei[ECNT + e]], 1);
}
__global__ void __launch_bounds__(1024) k_scan1() {
    __shared__ int wsum[32];
    int t = threadIdx.x;
    int base = blockIdx.x * SCAN_CH + t * 4;
    int v0 = g_deg[base], v1 = g_deg[base + 1], v2 = g_deg[base + 2], v3 = g_deg[base + 3];
    int s = v0 + v1 + v2 + v3;
    int lane = t & 31, wid = t >> 5;
    int incl = s;
#pragma unroll
    for (int off = 1; off < 32; off <<= 1) {
        int n = __shfl_up_sync(0xffffffffu, incl, off);
        if (lane >= off) incl += n;
    }
    if (lane == 31) wsum[wid] = incl;
    __syncthreads();
    if (wid == 0) {
        int wv = wsum[lane];
        int wincl = wv;
#pragma unroll
        for (int off = 1; off < 32; off <<= 1) {
            int n = __shfl_up_sync(0xffffffffu, wincl, off);
            if (lane >= off) wincl += n;
        }
        wsum[lane] = wincl - wv;
        if (lane == 31) g_bsum[blockIdx.x] = wincl;
    }
    __syncthreads();
    int excl = wsum[wid] + (incl - s);
    g_rowptr[base]     = excl;
    g_rowptr[base + 1] = excl + v0;
    g_rowptr[base + 2] = excl + v0 + v1;
    g_rowptr[base + 3] = excl + v0 + v1 + v2;
}
__global__ void __launch_bounds__(256) k_scan2() {
    __shared__ int s[256];
    int t = threadIdx.x;
    s[t] = (t < SCAN_NB) ? g_bsum[t] : 0;
    __syncthreads();
    if (t == 0) {
        int run = 0;
        for (int i = 0; i < SCAN_NB; i++) { int v = s[i]; s[i] = run; run += v; }
    }
    __syncthreads();
    if (t < SCAN_NB) g_bsum[t] = s[t];
}
__global__ void __launch_bounds__(256) k_scan3() {
    int i = blockIdx.x * blockDim.x + threadIdx.x;
    if (i < NTOT) {
        int r = g_rowptr[i] + g_bsum[i >> 12];
        g_rowptr[i] = r;
        g_cursor[i] = r;
    }
}
__global__ void __launch_bounds__(256) k_fill(const int* __restrict__ ei) {
    int e = blockIdx.x * blockDim.x + threadIdx.x;
    if (e < ECNT) {
        int s = ei[e];
        int d = ei[ECNT + e];
        int p = atomicAdd(&g_cursor[d], 1);
        g_col[p] = s;
    }
}

// ---------------- layer-0 projection: x[13] -> pa = x@wl0, ps = x@wr0 + bl0 ----------------
__global__ void __launch_bounds__(256) k_proj0(const float* __restrict__ x,
                                               const float* __restrict__ wl0,
                                               const float* __restrict__ wr0,
                                               const float* __restrict__ bl0,
                                               float* __restrict__ paOut,
                                               float* __restrict__ psOut) {
    __shared__ float2 wS[13 * 32];
    __shared__ float  blS[32];
    int tid = threadIdx.x, t = tid & 31, w = tid >> 5;
    for (int i = tid; i < 13 * 32; i += 256)
        wS[i] = make_float2(wl0[i], wr0[i]);
    if (tid < 32) blS[tid] = bl0[tid];
    __syncthreads();

    int wg = blockIdx.x * 8 + w;          // 56320 warps, 16 nodes each
    for (int it = 0; it < 16; it++) {
        int n = wg * 16 + it;
        float xv = (t < 13) ? x[(size_t)n * 13 + t] : 0.f;
        float apa = 0.f, aps = 0.f;
#pragma unroll
        for (int k = 0; k < 13; k++) {
            float xk = __shfl_sync(0xffffffffu, xv, k);
            float2 w2 = wS[k * 32 + t];
            apa = fmaf(xk, w2.x, apa);
            aps = fmaf(xk, w2.y, aps);
        }
        size_t idx = (size_t)n * 32 + t;
        paOut[idx] = apa;
        __stcs(&psOut[idx], aps + blS[t]);
    }
}

// ---------------- fused aggregate + selu + jk + project-next ----------------
// o = selu(mean_j paIn[j] + psIn[i]); jk update; pa' = o@wl, ps' = o@wr + bl.
// Streams (ps, jk, ps') use evict-first hints so the gathered pa stays in L2.
template <int MODE>
__global__ void __launch_bounds__(256) k_aggproj(const float* __restrict__ paIn,
                                                 const float* __restrict__ psIn,
                                                 float* __restrict__ paOut,
                                                 float* __restrict__ psOut,
                                                 const float* __restrict__ wl,
                                                 const float* __restrict__ wr,
                                                 const float* __restrict__ bl) {
    __shared__ float2 wS[32 * 32];
    __shared__ float  blS[32];
    int tid = threadIdx.x, t = tid & 31, w = tid >> 5;
    for (int i = tid; i < 1024; i += 256)
        wS[i] = make_float2(wl[i], wr[i]);
    if (tid < 32) blS[tid] = bl[tid];
    __syncthreads();

    int wg = blockIdx.x * 8 + w;          // 56320 warps * 16 nodes = NTOT

    // pipeline: preload node it+1's CSR info while processing node it
    int nN = wg * 16;
    int sN = g_rowptr[nN];
    int dN = g_deg[nN];
    int colrN = (t < min(dN, 32)) ? g_col[sN + t] : 0;

    for (int it = 0; it < 16; it++) {
        int n = wg * 16 + it;
        int s = sN, d = dN, colr = colrN;
        if (it < 15) {
            int nn = n + 1;
            sN = g_rowptr[nn];
            dN = g_deg[nn];
            colrN = (t < min(dN, 32)) ? g_col[sN + t] : 0;
        }

        int dlim = min(d, 32);
        float acc = 0.f;
        int e = 0;
        for (; e + 4 <= dlim; e += 4) {
            int c0 = __shfl_sync(0xffffffffu, colr, e);
            int c1 = __shfl_sync(0xffffffffu, colr, e + 1);
            int c2 = __shfl_sync(0xffffffffu, colr, e + 2);
            int c3 = __shfl_sync(0xffffffffu, colr, e + 3);
            float v0 = __ldg(&paIn[(size_t)c0 * 32 + t]);
            float v1 = __ldg(&paIn[(size_t)c1 * 32 + t]);
            float v2 = __ldg(&paIn[(size_t)c2 * 32 + t]);
            float v3 = __ldg(&paIn[(size_t)c3 * 32 + t]);
            acc += (v0 + v1) + (v2 + v3);
        }
        for (; e < dlim; e++) {
            int c = __shfl_sync(0xffffffffu, colr, e);
            acc += __ldg(&paIn[(size_t)c * 32 + t]);
        }
        for (int e2 = 32; e2 < d; e2++) {       // pathological-degree tail
            int c = g_col[s + e2];
            acc += __ldg(&paIn[(size_t)c * 32 + t]);
        }

        size_t idx = (size_t)n * 32 + t;
        float o = acc * (1.f / (float)max(d, 1)) + __ldcs(&psIn[idx]);
        o = selu_f(o);

        if (MODE == 0) __stcs(&g_jk[idx], o);
        else           __stcs(&g_jk[idx], fmaxf(__ldcs(&g_jk[idx]), o));

        float apa = 0.f, aps = 0.f;
#pragma unroll
        for (int k = 0; k < 32; k++) {
            float ok = __shfl_sync(0xffffffffu, o, k);
            float2 w2 = wS[k * 32 + t];
            apa = fmaf(ok, w2.x, apa);
            aps = fmaf(ok, w2.y, aps);
        }
        paOut[idx] = apa;
        __stcs(&psOut[idx], aps + blS[t]);
    }
}

// ---------------- attention + fused final SAGE layer ----------------
// keys_k = selu(max(jk_k, selu(mean_j paIn[j] + psIn[k])))  computed in-warp.
__device__ __forceinline__ int sel6(const int o0, const int o1, const int o2,
                                    const int o3, const int o4, const int o5, int si) {
    int r = o0;
    r = (si == 1) ? o1 : r;
    r = (si == 2) ? o2 : r;
    r = (si == 3) ? o3 : r;
    r = (si == 4) ? o4 : r;
    r = (si == 5) ? o5 : r;
    return r;
}

__global__ void __launch_bounds__(128) k_attn(const float* __restrict__ x,
                                              const int* __restrict__ shuf,
                                              const float* __restrict__ paIn,
                                              const float* __restrict__ psIn,
                                              const float* __restrict__ wfc,
                                              const float* __restrict__ bfc,
                                              float* __restrict__ out) {
    __shared__ float sA[1024], sW2[1024], sU[32], sV[32], sB2[32];
    __shared__ float sKeys[4][55 * 33];
    __shared__ float sQa[4][6 * 33];
    __shared__ float sKb[4][56];
    __shared__ float sAt[4][6 * 56];

    int tid = threadIdx.x, t = tid & 31, w = tid >> 5;

    for (int i = tid; i < 1024; i += 128) { sA[i] = g_A[i]; sW2[i] = g_W2[i]; }
    if (tid < 32) { sU[tid] = g_u[tid]; sV[tid] = g_v[tid]; sB2[tid] = g_b2[tid]; }
    __syncthreads();

    float cterm = g_c[0];
    int g = blockIdx.x * 4 + w;
    int nbase = g * NNODES;

    unsigned b0 = __ballot_sync(0xffffffffu, x[(size_t)(nbase + t) * 13 + 10] > 0.5f);
    unsigned b1 = __ballot_sync(0xffffffffu,
                                (t < 23) ? (x[(size_t)(nbase + 32 + t) * 13 + 10] > 0.5f) : false);
    int ord[6];
#pragma unroll
    for (int j = 0; j < 6; j++) {
        if (b0) { int p = __ffs(b0) - 1; b0 &= b0 - 1; ord[j] = p; }
        else    { int p = __ffs(b1) - 1; b1 &= b1 - 1; ord[j] = 32 + p; }
    }
    int qr[6];
#pragma unroll
    for (int j = 0; j < 6; j++) {
        int si = shuf[(size_t)g * 6 + j];
        qr[j] = sel6(ord[0], ord[1], ord[2], ord[3], ord[4], ord[5], si);
    }

    // --- fused layer-5 aggregation + jk max + selu -> keys (pipelined) ---
    {
        int nN = nbase;
        int sN = g_rowptr[nN];
        int dN = g_deg[nN];
        int colrN = (t < min(dN, 32)) ? g_col[sN + t] : 0;
        for (int k = 0; k < 55; k++) {
            int n = nbase + k;
            int s = sN, d = dN, colr = colrN;
            if (k < 54) {
                int nn = n + 1;
                sN = g_rowptr[nn];
                dN = g_deg[nn];
                colrN = (t < min(dN, 32)) ? g_col[sN + t] : 0;
            }
            int dlim = min(d, 32);
            float acc = 0.f;
            int e = 0;
            for (; e + 4 <= dlim; e += 4) {
                int c0 = __shfl_sync(0xffffffffu, colr, e);
                int c1 = __shfl_sync(0xffffffffu, colr, e + 1);
                int c2 = __shfl_sync(0xffffffffu, colr, e + 2);
                int c3 = __shfl_sync(0xffffffffu, colr, e + 3);
                float v0 = __ldg(&paIn[(size_t)c0 * 32 + t]);
                float v1 = __ldg(&paIn[(size_t)c1 * 32 + t]);
                float v2 = __ldg(&paIn[(size_t)c2 * 32 + t]);
                float v3 = __ldg(&paIn[(size_t)c3 * 32 + t]);
                acc += (v0 + v1) + (v2 + v3);
            }
            for (; e < dlim; e++) {
                int c = __shfl_sync(0xffffffffu, colr, e);
                acc += __ldg(&paIn[(size_t)c * 32 + t]);
            }
            for (int e2 = 32; e2 < d; e2++) {
                int c = g_col[s + e2];
                acc += __ldg(&paIn[(size_t)c * 32 + t]);
            }
            size_t idx = (size_t)n * 32 + t;
            float o = acc * (1.f / (float)max(d, 1)) + __ldcs(&psIn[idx]);
            o = selu_f(o);
            float jkv = fmaxf(__ldcs(&g_jk[idx]), o);
            sKeys[w][k * 33 + t] = selu_f(jkv);
        }
    }
    __syncwarp();

    {
        float acc = cterm;
#pragma unroll
        for (int d = 0; d < 32; d++) acc += sKeys[w][t * 33 + d] * sV[d];
        sKb[w][t] = acc;
        if (t < 23) {
            float a2 = cterm;
#pragma unroll
            for (int d = 0; d < 32; d++) a2 += sKeys[w][(t + 32) * 33 + d] * sV[d];
            sKb[w][t + 32] = a2;
        }
    }

    float qu[6];
#pragma unroll
    for (int q = 0; q < 6; q++) {
        const float* kr = &sKeys[w][qr[q] * 33];
        float pp = kr[t] * sU[t];
#pragma unroll
        for (int off = 16; off; off >>= 1) pp += __shfl_xor_sync(0xffffffffu, pp, off);
        qu[q] = pp;
        float a = 0.f;
#pragma unroll
        for (int d = 0; d < 32; d++) a += kr[d] * sA[d * 32 + t];
        sQa[w][q * 33 + t] = a;
    }
    __syncwarp();

    const float isq = 0.17677669529663687f;  // 1/sqrt(32)
#pragma unroll
    for (int q = 0; q < 6; q++) {
        const float* qa = &sQa[w][q * 33];
        int k1 = (t < 23) ? (t + 32) : 54;
        float s0 = qu[q] + sKb[w][t];
        float s1 = qu[q] + sKb[w][k1];
#pragma unroll
        for (int d = 0; d < 32; d++) {
            float qv = qa[d];
            s0 += qv * sKeys[w][t * 33 + d];
            s1 += qv * sKeys[w][k1 * 33 + d];
        }
        s0 *= isq; s1 *= isq;
        if (t >= 23) s1 = -1e30f;
        float m = fmaxf(s0, s1);
#pragma unroll
        for (int off = 16; off; off >>= 1) m = fmaxf(m, __shfl_xor_sync(0xffffffffu, m, off));
        float e0 = __expf(s0 - m);
        float e1 = (t < 23) ? __expf(s1 - m) : 0.f;
        float sum = e0 + e1;
#pragma unroll
        for (int off = 16; off; off >>= 1) sum += __shfl_xor_sync(0xffffffffu, sum, off);
        float inv = 1.f / sum;
        sAt[w][q * 56 + t] = e0 * inv;
        if (t < 23) sAt[w][q * 56 + t + 32] = e1 * inv;
    }
    __syncwarp();

#pragma unroll
    for (int q = 0; q < 6; q++) {
        float c2 = 0.f;
        for (int k = 0; k < 55; k++) c2 += sAt[w][q * 56 + k] * sKeys[w][k * 33 + t];
        sQa[w][q * 33 + t] = c2;
    }
    __syncwarp();

#pragma unroll
    for (int q = 0; q < 6; q++) {
        float o = sB2[t];
#pragma unroll
        for (int d = 0; d < 32; d++) o += sQa[w][q * 33 + d] * sW2[d * 32 + t];
        sKeys[w][q * 32 + t] = selu_f(o);
    }
    __syncwarp();

    float pj[6] = {0.f, 0.f, 0.f, 0.f, 0.f, 0.f};
#pragma unroll
    for (int i = 0; i < 6; i++) {
        int e = i * 32 + t;
        float v = sKeys[w][e];
#pragma unroll
        for (int j = 0; j < 6; j++) pj[j] += v * wfc[e * 6 + j];
    }
#pragma unroll
    for (int j = 0; j < 6; j++) {
#pragma unroll
        for (int off = 16; off; off >>= 1) pj[j] += __shfl_xor_sync(0xffffffffu, pj[j], off);
    }
    if (t == 0) {
#pragma unroll
        for (int j = 0; j < 6; j++) out[(size_t)g * 6 + j] = pj[j] + bfc[j];
    }
}

// ---------------- launch ----------------
extern "C" void kernel_launch(void* const* d_in, const int* in_sizes, int n_in,
                              void* d_out, int out_size) {
    const float* x    = (const float*)d_in[0];
    const int*   ei   = (const int*)d_in[1];     // int32 (JAX demotes int64)
    const int*   shuf = (const int*)d_in[2];     // int32
    const float* wl0 = (const float*)d_in[3];
    const float* bl0 = (const float*)d_in[4];
    const float* wr0 = (const float*)d_in[5];
    const float* wl  = (const float*)d_in[6];
    const float* bl  = (const float*)d_in[7];
    const float* wr  = (const float*)d_in[8];
    const float* wq  = (const float*)d_in[9];
    const float* bq  = (const float*)d_in[10];
    const float* wk  = (const float*)d_in[11];
    const float* bk  = (const float*)d_in[12];
    const float* wv  = (const float*)d_in[13];
    const float* bv  = (const float*)d_in[14];
    const float* wo  = (const float*)d_in[15];
    const float* bo  = (const float*)d_in[16];
    const float* wfc = (const float*)d_in[17];
    const float* bfc = (const float*)d_in[18];
    float* out = (float*)d_out;

    float *paA, *psA, *paB, *psB;
    cudaGetSymbolAddress((void**)&paA, g_paA);
    cudaGetSymbolAddress((void**)&psA, g_psA);
    cudaGetSymbolAddress((void**)&paB, g_paB);
    cudaGetSymbolAddress((void**)&psB, g_psB);

    k_prep<<<1, 256>>>(wq, bq, wk, bk, wv, bv, wo, bo);
    k_zero<<<(NTOT + 255) / 256, 256>>>();
    k_hist<<<(ECNT + 255) / 256, 256>>>(ei);
    k_scan1<<<SCAN_NB, 1024>>>();
    k_scan2<<<1, 256>>>();
    k_scan3<<<(NTOT + 255) / 256, 256>>>();
    k_fill<<<(ECNT + 255) / 256, 256>>>(ei);

    // layer-1 inputs
    k_proj0<<<AGG_BLOCKS, 256>>>(x, wl0, wr0, bl0, paA, psA);
    // layer 1 (jk = h1) + project layer-2 inputs
    k_aggproj<0><<<AGG_BLOCKS, 256>>>(paA, psA, paB, psB,
                                      wl + 0 * 1024, wr + 0 * 1024, bl + 0 * 32);
    // layers 2..4 (jk = max) + project next
    k_aggproj<1><<<AGG_BLOCKS, 256>>>(paB, psB, paA, psA,
                                      wl + 1 * 1024, wr + 1 * 1024, bl + 1 * 32);
    k_aggproj<1><<<AGG_BLOCKS, 256>>>(paA, psA, paB, psB,
                                      wl + 2 * 1024, wr + 2 * 1024, bl + 2 * 32);
    k_aggproj<1><<<AGG_BLOCKS, 256>>>(paB, psB, paA, psA,
                                      wl + 3 * 1024, wr + 3 * 1024, bl + 3 * 32);

    // layer 5 fused into attention (gathers paA/psA, maxes with jk in-register)
    k_attn<<<NB / 4, 128>>>(x, shuf, paA, psA, wfc, bfc, out);
}

// round 11
// speedup vs baseline: 1.2357x; 1.2357x over previous
#include <cuda_runtime.h>
#include <cuda_fp16.h>

#define NB     16384
#define NNODES 55
#define NTOT   (NB * NNODES)      // 901120
#define ECNT   (4 * NTOT)         // 3604480
#define SCAN_CH 4096
#define SCAN_NB (NTOT / SCAN_CH)  // 220 exactly

#define AGG_BLOCKS 7040           // 7040 * 8 warps * 16 nodes = 901120

// ---------------- device scratch ----------------
__device__ __half g_paA[NTOT * 32];
__device__ __half g_paB[NTOT * 32];
__device__ float  g_psA[NTOT * 32];
__device__ float  g_psB[NTOT * 32];
__device__ float  g_jk[NTOT * 32];
__device__ int    g_deg[NTOT];
__device__ int    g_rowptr[NTOT];
__device__ int    g_cursor[NTOT];
__device__ int    g_col[ECNT];
__device__ int    g_bsum[256];
__device__ float  g_A[1024], g_W2[1024], g_u[32], g_v[32], g_b2[32], g_c[1];

__device__ __forceinline__ float selu_f(float x) {
    const float sc = 1.0507009873554805f;
    const float sa = 1.7580993408473766f;  // sc * alpha
    return x > 0.f ? sc * x : sa * expm1f(x);
}

// ---------------- attention precompute ----------------
__global__ void __launch_bounds__(256) k_prep(
        const float* __restrict__ wq, const float* __restrict__ bq,
        const float* __restrict__ wk, const float* __restrict__ bk,
        const float* __restrict__ wv, const float* __restrict__ bv,
        const float* __restrict__ wo, const float* __restrict__ bo) {
    int tid = threadIdx.x;
    for (int i = tid; i < 1024; i += 256) {
        int d = i >> 5, e = i & 31;
        float a = 0.f, w2 = 0.f;
        for (int o = 0; o < 32; o++) {
            a  += wq[d * 32 + o] * wk[e * 32 + o];
            w2 += wv[d * 32 + o] * wo[o * 32 + e];
        }
        g_A[d * 32 + e]  = a;
        g_W2[d * 32 + e] = w2;
    }
    if (tid < 32) {
        float u = 0.f, v = 0.f, b2 = 0.f;
        for (int o = 0; o < 32; o++) {
            u  += wq[tid * 32 + o] * bk[o];
            v  += wk[tid * 32 + o] * bq[o];
            b2 += bv[o] * wo[o * 32 + tid];
        }
        g_u[tid] = u; g_v[tid] = v; g_b2[tid] = b2 + bo[tid];
    }
    if (tid == 0) {
        float c = 0.f;
        for (int o = 0; o < 32; o++) c += bq[o] * bk[o];
        g_c[0] = c;
    }
}

// ---------------- CSR build ----------------
__global__ void __launch_bounds__(256) k_zero() {
    int i = blockIdx.x * blockDim.x + threadIdx.x;
    if (i < NTOT) g_deg[i] = 0;
}
__global__ void __launch_bounds__(256) k_hist(const int* __restrict__ ei) {
    int e = blockIdx.x * blockDim.x + threadIdx.x;
    if (e < ECNT) atomicAdd(&g_deg[ei[ECNT + e]], 1);
}
__global__ void __launch_bounds__(1024) k_scan1() {
    __shared__ int wsum[32];
    int t = threadIdx.x;
    int base = blockIdx.x * SCAN_CH + t * 4;
    int v0 = g_deg[base], v1 = g_deg[base + 1], v2 = g_deg[base + 2], v3 = g_deg[base + 3];
    int s = v0 + v1 + v2 + v3;
    int lane = t & 31, wid = t >> 5;
    int incl = s;
#pragma unroll
    for (int off = 1; off < 32; off <<= 1) {
        int n = __shfl_up_sync(0xffffffffu, incl, off);
        if (lane >= off) incl += n;
    }
    if (lane == 31) wsum[wid] = incl;
    __syncthreads();
    if (wid == 0) {
        int wv = wsum[lane];
        int wincl = wv;
#pragma unroll
        for (int off = 1; off < 32; off <<= 1) {
            int n = __shfl_up_sync(0xffffffffu, wincl, off);
            if (lane >= off) wincl += n;
        }
        wsum[lane] = wincl - wv;
        if (lane == 31) g_bsum[blockIdx.x] = wincl;
    }
    __syncthreads();
    int excl = wsum[wid] + (incl - s);
    g_rowptr[base]     = excl;
    g_rowptr[base + 1] = excl + v0;
    g_rowptr[base + 2] = excl + v0 + v1;
    g_rowptr[base + 3] = excl + v0 + v1 + v2;
}
__global__ void __launch_bounds__(256) k_scan2() {
    __shared__ int s[256];
    int t = threadIdx.x;
    s[t] = (t < SCAN_NB) ? g_bsum[t] : 0;
    __syncthreads();
    if (t == 0) {
        int run = 0;
        for (int i = 0; i < SCAN_NB; i++) { int v = s[i]; s[i] = run; run += v; }
    }
    __syncthreads();
    if (t < SCAN_NB) g_bsum[t] = s[t];
}
__global__ void __launch_bounds__(256) k_scan3() {
    int i = blockIdx.x * blockDim.x + threadIdx.x;
    if (i < NTOT) {
        int r = g_rowptr[i] + g_bsum[i >> 12];
        g_rowptr[i] = r;
        g_cursor[i] = r;
    }
}
__global__ void __launch_bounds__(256) k_fill(const int* __restrict__ ei) {
    int e = blockIdx.x * blockDim.x + threadIdx.x;
    if (e < ECNT) {
        int s = ei[e];
        int d = ei[ECNT + e];
        int p = atomicAdd(&g_cursor[d], 1);
        g_col[p] = s;
    }
}

// ---------------- layer-0 projection: x[13] -> pa(half) = x@wl0, ps = x@wr0 + bl0 ----------------
__global__ void __launch_bounds__(256) k_proj0(const float* __restrict__ x,
                                               const float* __restrict__ wl0,
                                               const float* __restrict__ wr0,
                                               const float* __restrict__ bl0,
                                               __half* __restrict__ paOut,
                                               float* __restrict__ psOut) {
    __shared__ float2 wS[13 * 32];
    __shared__ float  blS[32];
    int tid = threadIdx.x, t = tid & 31, w = tid >> 5;
    for (int i = tid; i < 13 * 32; i += 256)
        wS[i] = make_float2(wl0[i], wr0[i]);
    if (tid < 32) blS[tid] = bl0[tid];
    __syncthreads();

    int wg = blockIdx.x * 8 + w;          // 56320 warps, 16 nodes each
    for (int it = 0; it < 16; it++) {
        int n = wg * 16 + it;
        float xv = (t < 13) ? x[(size_t)n * 13 + t] : 0.f;
        float apa = 0.f, aps = 0.f;
#pragma unroll
        for (int k = 0; k < 13; k++) {
            float xk = __shfl_sync(0xffffffffu, xv, k);
            float2 w2 = wS[k * 32 + t];
            apa = fmaf(xk, w2.x, apa);
            aps = fmaf(xk, w2.y, aps);
        }
        size_t idx = (size_t)n * 32 + t;
        paOut[idx] = __float2half_rn(apa);
        __stcs(&psOut[idx], aps + blS[t]);
    }
}

// ---------------- fused aggregate + selu + jk + project-next ----------------
// o = selu(mean_j paIn[j] + psIn[i]); jk update; pa' = half(o@wl), ps' = o@wr + bl.
// Streams (ps, jk, ps') use evict-first hints so the gathered half pa stays in L2.
template <int MODE, int DO_PROJ>
__global__ void __launch_bounds__(256) k_aggproj(const __half* __restrict__ paIn,
                                                 const float* __restrict__ psIn,
                                                 __half* __restrict__ paOut,
                                                 float* __restrict__ psOut,
                                                 const float* __restrict__ wl,
                                                 const float* __restrict__ wr,
                                                 const float* __restrict__ bl) {
    __shared__ float2 wS[32 * 32];
    __shared__ float  blS[32];
    int tid = threadIdx.x, t = tid & 31, w = tid >> 5;
    if (DO_PROJ) {
        for (int i = tid; i < 1024; i += 256)
            wS[i] = make_float2(wl[i], wr[i]);
        if (tid < 32) blS[tid] = bl[tid];
        __syncthreads();
    }

    int wg = blockIdx.x * 8 + w;          // 56320 warps * 16 nodes = NTOT

    // pipeline: preload node it+1's CSR info while processing node it
    int nN = wg * 16;
    int sN = g_rowptr[nN];
    int dN = g_deg[nN];
    int colrN = (t < min(dN, 32)) ? g_col[sN + t] : 0;

    for (int it = 0; it < 16; it++) {
        int n = wg * 16 + it;
        int s = sN, d = dN, colr = colrN;
        if (it < 15) {
            int nn = n + 1;
            sN = g_rowptr[nn];
            dN = g_deg[nn];
            colrN = (t < min(dN, 32)) ? g_col[sN + t] : 0;
        }

        int dlim = min(d, 32);
        float acc = 0.f;
        int e = 0;
        for (; e + 4 <= dlim; e += 4) {
            int c0 = __shfl_sync(0xffffffffu, colr, e);
            int c1 = __shfl_sync(0xffffffffu, colr, e + 1);
            int c2 = __shfl_sync(0xffffffffu, colr, e + 2);
            int c3 = __shfl_sync(0xffffffffu, colr, e + 3);
            float v0 = __half2float(__ldg(&paIn[(size_t)c0 * 32 + t]));
            float v1 = __half2float(__ldg(&paIn[(size_t)c1 * 32 + t]));
            float v2 = __half2float(__ldg(&paIn[(size_t)c2 * 32 + t]));
            float v3 = __half2float(__ldg(&paIn[(size_t)c3 * 32 + t]));
            acc += (v0 + v1) + (v2 + v3);
        }
        for (; e < dlim; e++) {
            int c = __shfl_sync(0xffffffffu, colr, e);
            acc += __half2float(__ldg(&paIn[(size_t)c * 32 + t]));
        }
        for (int e2 = 32; e2 < d; e2++) {       // pathological-degree tail
            int c = g_col[s + e2];
            acc += __half2float(__ldg(&paIn[(size_t)c * 32 + t]));
        }

        size_t idx = (size_t)n * 32 + t;
        float o = acc * (1.f / (float)max(d, 1)) + __ldcs(&psIn[idx]);
        o = selu_f(o);

        if (MODE == 0) __stcs(&g_jk[idx], o);
        else           __stcs(&g_jk[idx], fmaxf(__ldcs(&g_jk[idx]), o));

        if (DO_PROJ) {
            float apa = 0.f, aps = 0.f;
#pragma unroll
            for (int k = 0; k < 32; k++) {
                float ok = __shfl_sync(0xffffffffu, o, k);
                float2 w2 = wS[k * 32 + t];
                apa = fmaf(ok, w2.x, apa);
                aps = fmaf(ok, w2.y, aps);
            }
            paOut[idx] = __float2half_rn(apa);
            __stcs(&psOut[idx], aps + blS[t]);
        }
    }
}

// ---------------- attention (1 warp per graph, 4 graphs per 128-thread block) ----------------
__device__ __forceinline__ int sel6(const int o0, const int o1, const int o2,
                                    const int o3, const int o4, const int o5, int si) {
    int r = o0;
    r = (si == 1) ? o1 : r;
    r = (si == 2) ? o2 : r;
    r = (si == 3) ? o3 : r;
    r = (si == 4) ? o4 : r;
    r = (si == 5) ? o5 : r;
    return r;
}

__global__ void __launch_bounds__(128) k_attn(const float* __restrict__ x,
                                              const int* __restrict__ shuf,
                                              const float* __restrict__ wfc,
                                              const float* __restrict__ bfc,
                                              float* __restrict__ out) {
    __shared__ float sA[1024], sW2[1024], sU[32], sV[32], sB2[32];
    __shared__ float sKeys[4][55 * 33];
    __shared__ float sQa[4][6 * 33];
    __shared__ float sKb[4][56];
    __shared__ float sAt[4][6 * 56];

    int tid = threadIdx.x, t = tid & 31, w = tid >> 5;

    for (int i = tid; i < 1024; i += 128) { sA[i] = g_A[i]; sW2[i] = g_W2[i]; }
    if (tid < 32) { sU[tid] = g_u[tid]; sV[tid] = g_v[tid]; sB2[tid] = g_b2[tid]; }
    __syncthreads();

    float cterm = g_c[0];
    int g = blockIdx.x * 4 + w;
    int nbase = g * NNODES;

    unsigned b0 = __ballot_sync(0xffffffffu, x[(size_t)(nbase + t) * 13 + 10] > 0.5f);
    unsigned b1 = __ballot_sync(0xffffffffu,
                                (t < 23) ? (x[(size_t)(nbase + 32 + t) * 13 + 10] > 0.5f) : false);
    int ord[6];
#pragma unroll
    for (int j = 0; j < 6; j++) {
        if (b0) { int p = __ffs(b0) - 1; b0 &= b0 - 1; ord[j] = p; }
        else    { int p = __ffs(b1) - 1; b1 &= b1 - 1; ord[j] = 32 + p; }
    }
    int qr[6];
#pragma unroll
    for (int j = 0; j < 6; j++) {
        int si = shuf[(size_t)g * 6 + j];
        qr[j] = sel6(ord[0], ord[1], ord[2], ord[3], ord[4], ord[5], si);
    }

    for (int k = 0; k < 55; k++)
        sKeys[w][k * 33 + t] = selu_f(g_jk[(size_t)(nbase + k) * 32 + t]);
    __syncwarp();

    {
        float acc = cterm;
#pragma unroll
        for (int d = 0; d < 32; d++) acc += sKeys[w][t * 33 + d] * sV[d];
        sKb[w][t] = acc;
        if (t < 23) {
            float a2 = cterm;
#pragma unroll
            for (int d = 0; d < 32; d++) a2 += sKeys[w][(t + 32) * 33 + d] * sV[d];
            sKb[w][t + 32] = a2;
        }
    }

    float qu[6];
#pragma unroll
    for (int q = 0; q < 6; q++) {
        const float* kr = &sKeys[w][qr[q] * 33];
        float pp = kr[t] * sU[t];
#pragma unroll
        for (int off = 16; off; off >>= 1) pp += __shfl_xor_sync(0xffffffffu, pp, off);
        qu[q] = pp;
        float a = 0.f;
#pragma unroll
        for (int d = 0; d < 32; d++) a += kr[d] * sA[d * 32 + t];
        sQa[w][q * 33 + t] = a;
    }
    __syncwarp();

    const float isq = 0.17677669529663687f;  // 1/sqrt(32)
#pragma unroll
    for (int q = 0; q < 6; q++) {
        const float* qa = &sQa[w][q * 33];
        int k1 = (t < 23) ? (t + 32) : 54;
        float s0 = qu[q] + sKb[w][t];
        float s1 = qu[q] + sKb[w][k1];
#pragma unroll
        for (int d = 0; d < 32; d++) {
            float qv = qa[d];
            s0 += qv * sKeys[w][t * 33 + d];
            s1 += qv * sKeys[w][k1 * 33 + d];
        }
        s0 *= isq; s1 *= isq;
        if (t >= 23) s1 = -1e30f;
        float m = fmaxf(s0, s1);
#pragma unroll
        for (int off = 16; off; off >>= 1) m = fmaxf(m, __shfl_xor_sync(0xffffffffu, m, off));
        float e0 = __expf(s0 - m);
        float e1 = (t < 23) ? __expf(s1 - m) : 0.f;
        float sum = e0 + e1;
#pragma unroll
        for (int off = 16; off; off >>= 1) sum += __shfl_xor_sync(0xffffffffu, sum, off);
        float inv = 1.f / sum;
        sAt[w][q * 56 + t] = e0 * inv;
        if (t < 23) sAt[w][q * 56 + t + 32] = e1 * inv;
    }
    __syncwarp();

#pragma unroll
    for (int q = 0; q < 6; q++) {
        float c2 = 0.f;
        for (int k = 0; k < 55; k++) c2 += sAt[w][q * 56 + k] * sKeys[w][k * 33 + t];
        sQa[w][q * 33 + t] = c2;
    }
    __syncwarp();

#pragma unroll
    for (int q = 0; q < 6; q++) {
        float o = sB2[t];
#pragma unroll
        for (int d = 0; d < 32; d++) o += sQa[w][q * 33 + d] * sW2[d * 32 + t];
        sKeys[w][q * 32 + t] = selu_f(o);
    }
    __syncwarp();

    float pj[6] = {0.f, 0.f, 0.f, 0.f, 0.f, 0.f};
#pragma unroll
    for (int i = 0; i < 6; i++) {
        int e = i * 32 + t;
        float v = sKeys[w][e];
#pragma unroll
        for (int j = 0; j < 6; j++) pj[j] += v * wfc[e * 6 + j];
    }
#pragma unroll
    for (int j = 0; j < 6; j++) {
#pragma unroll
        for (int off = 16; off; off >>= 1) pj[j] += __shfl_xor_sync(0xffffffffu, pj[j], off);
    }
    if (t == 0) {
#pragma unroll
        for (int j = 0; j < 6; j++) out[(size_t)g * 6 + j] = pj[j] + bfc[j];
    }
}

// ---------------- launch ----------------
extern "C" void kernel_launch(void* const* d_in, const int* in_sizes, int n_in,
                              void* d_out, int out_size) {
    const float* x    = (const float*)d_in[0];
    const int*   ei   = (const int*)d_in[1];     // int32 (JAX demotes int64)
    const int*   shuf = (const int*)d_in[2];     // int32
    const float* wl0 = (const float*)d_in[3];
    const float* bl0 = (const float*)d_in[4];
    const float* wr0 = (const float*)d_in[5];
    const float* wl  = (const float*)d_in[6];
    const float* bl  = (const float*)d_in[7];
    const float* wr  = (const float*)d_in[8];
    const float* wq  = (const float*)d_in[9];
    const float* bq  = (const float*)d_in[10];
    const float* wk  = (const float*)d_in[11];
    const float* bk  = (const float*)d_in[12];
    const float* wv  = (const float*)d_in[13];
    const float* bv  = (const float*)d_in[14];
    const float* wo  = (const float*)d_in[15];
    const float* bo  = (const float*)d_in[16];
    const float* wfc = (const float*)d_in[17];
    const float* bfc = (const float*)d_in[18];
    float* out = (float*)d_out;

    __half *paA, *paB;
    float *psA, *psB;
    cudaGetSymbolAddress((void**)&paA, g_paA);
    cudaGetSymbolAddress((void**)&paB, g_paB);
    cudaGetSymbolAddress((void**)&psA, g_psA);
    cudaGetSymbolAddress((void**)&psB, g_psB);

    k_prep<<<1, 256>>>(wq, bq, wk, bk, wv, bv, wo, bo);
    k_zero<<<(NTOT + 255) / 256, 256>>>();
    k_hist<<<(ECNT + 255) / 256, 256>>>(ei);
    k_scan1<<<SCAN_NB, 1024>>>();
    k_scan2<<<1, 256>>>();
    k_scan3<<<(NTOT + 255) / 256, 256>>>();
    k_fill<<<(ECNT + 255) / 256, 256>>>(ei);

    // layer-1 inputs
    k_proj0<<<AGG_BLOCKS, 256>>>(x, wl0, wr0, bl0, paA, psA);
    // layer 1 (jk = h1) + project layer-2 inputs
    k_aggproj<0, 1><<<AGG_BLOCKS, 256>>>(paA, psA, paB, psB,
                                         wl + 0 * 1024, wr + 0 * 1024, bl + 0 * 32);
    // layers 2..4 (jk = max) + project next
    k_aggproj<1, 1><<<AGG_BLOCKS, 256>>>(paB, psB, paA, psA,
                                         wl + 1 * 1024, wr + 1 * 1024, bl + 1 * 32);
    k_aggproj<1, 1><<<AGG_BLOCKS, 256>>>(paA, psA, paB, psB,
                                         wl + 2 * 1024, wr + 2 * 1024, bl + 2 * 32);
    k_aggproj<1, 1><<<AGG_BLOCKS, 256>>>(paB, psB, paA, psA,
                                         wl + 3 * 1024, wr + 3 * 1024, bl + 3 * 32);
    // layer 5: aggregate + jk only
    k_aggproj<1, 0><<<AGG_BLOCKS, 256>>>(paA, psA, nullptr, nullptr,
                                         nullptr, nullptr, nullptr);

    k_attn<<<NB / 4, 128>>>(x, shuf, wfc, bfc, out);
}